// round 1
// baseline (speedup 1.0000x reference)
#include <cuda_runtime.h>
#include <cstdint>

// Shapes (fixed by the problem)
#define BT   6          // b*t = 2*3
#define NN   4096       // nodes
#define DD   64         // di = do = de = 64
#define WC   8192       // 2*64*64 hypernet weight cols per node

// Scratch (device globals — no allocations allowed)
__device__ float g_E   [BT * NN * DD];   // layernormed embeddings, 6.3 MB
__device__ float g_W   [(size_t)NN * WC]; // per-node hypernet weights, 134 MB
__device__ float g_xg2 [BT * NN * DD];   // attention output, 6.3 MB
__device__ float g_bias[BT * DD];        // per-(b,t) bias

// ---------------------------------------------------------------------------
// K1: E[bt,n,:] = LayerNorm(node_emb[n,:] + time_emb[bt,:])  (warp per row)
// ---------------------------------------------------------------------------
__global__ __launch_bounds__(256) void k_ln(
    const float* __restrict__ node_emb, const float* __restrict__ time_emb,
    const float* __restrict__ gamma, const float* __restrict__ beta)
{
    int row  = blockIdx.x * 8 + (threadIdx.x >> 5);   // 0..BT*NN-1
    int lane = threadIdx.x & 31;
    if (row >= BT * NN) return;
    int bt = row >> 12;
    int n  = row & (NN - 1);

    float e0 = node_emb[n * DD + lane]       + time_emb[bt * DD + lane];
    float e1 = node_emb[n * DD + 32 + lane]  + time_emb[bt * DD + 32 + lane];
    float s  = e0 + e1;
    float s2 = e0 * e0 + e1 * e1;
    #pragma unroll
    for (int off = 16; off; off >>= 1) {
        s  += __shfl_xor_sync(0xffffffffu, s,  off);
        s2 += __shfl_xor_sync(0xffffffffu, s2, off);
    }
    float mu  = s * (1.0f / 64.0f);
    float var = s2 * (1.0f / 64.0f) - mu * mu;
    float rs  = rsqrtf(var + 1e-12f);
    float o0 = (e0 - mu) * rs * gamma[lane]      + beta[lane];
    float o1 = (e1 - mu) * rs * gamma[32 + lane] + beta[32 + lane];
    g_E[row * DD + lane]      = o0;
    g_E[row * DD + 32 + lane] = o1;
}

// ---------------------------------------------------------------------------
// K2: bias[bt,o] = time_emb[bt,:] . bias_pool[:,o]
// ---------------------------------------------------------------------------
__global__ void k_bias(const float* __restrict__ time_emb,
                       const float* __restrict__ bias_pool)
{
    int bt = blockIdx.x, o = threadIdx.x;
    float s = 0.f;
    #pragma unroll
    for (int d = 0; d < DD; d++) s += time_emb[bt * DD + d] * bias_pool[d * DD + o];
    g_bias[bt * DD + o] = s;
}

// ---------------------------------------------------------------------------
// K3: W[n, c] = node_emb[n,:] @ weights_pool[:, c]   (4096x64)@(64x8192)
//     Tile 128(n) x 64(c), 256 threads, 8x4 microtile, K=64 (single stage).
// ---------------------------------------------------------------------------
__global__ __launch_bounds__(256) void k_wgemm(
    const float* __restrict__ A,    // node_emb 4096x64
    const float* __restrict__ Bm)   // weights_pool as 64x8192
{
    __shared__ float As[64][128];   // [k][n]  32 KB
    __shared__ float Bs[64][64];    // [k][c]  16 KB
    int n0 = blockIdx.y * 128;
    int c0 = blockIdx.x * 64;
    int tid = threadIdx.x;

    // Load+transpose A tile: 128 rows x 16 float4
    #pragma unroll
    for (int p = 0; p < 8; p++) {
        int idx = p * 256 + tid;       // 0..2047
        int r   = idx >> 4;            // 0..127
        int c4  = idx & 15;            // 0..15
        float4 v = ((const float4*)A)[(size_t)(n0 + r) * 16 + c4];
        As[c4 * 4 + 0][r] = v.x;
        As[c4 * 4 + 1][r] = v.y;
        As[c4 * 4 + 2][r] = v.z;
        As[c4 * 4 + 3][r] = v.w;
    }
    // Load B tile: 64 rows x 16 float4
    #pragma unroll
    for (int p = 0; p < 4; p++) {
        int idx = p * 256 + tid;       // 0..1023
        int r   = idx >> 4;            // k
        int c4  = idx & 15;
        ((float4*)&Bs[r][0])[c4] = ((const float4*)(Bm + (size_t)r * WC + c0))[c4];
    }
    __syncthreads();

    int tx = tid & 15;   // col group (x4)
    int ty = tid >> 4;   // row group (x8)
    float acc[8][4];
    #pragma unroll
    for (int i = 0; i < 8; i++)
        #pragma unroll
        for (int j = 0; j < 4; j++) acc[i][j] = 0.f;

    #pragma unroll
    for (int k = 0; k < 64; k++) {
        float a[8], b[4];
        *(float4*)&a[0] = *(const float4*)&As[k][ty * 8 + 0];
        *(float4*)&a[4] = *(const float4*)&As[k][ty * 8 + 4];
        *(float4*)&b[0] = *(const float4*)&Bs[k][tx * 4];
        #pragma unroll
        for (int i = 0; i < 8; i++)
            #pragma unroll
            for (int j = 0; j < 4; j++) acc[i][j] += a[i] * b[j];
    }

    #pragma unroll
    for (int i = 0; i < 8; i++) {
        int n = n0 + ty * 8 + i;
        float4 v = make_float4(acc[i][0], acc[i][1], acc[i][2], acc[i][3]);
        *(float4*)(g_W + (size_t)n * WC + c0 + tx * 4) = v;
    }
}

// ---------------------------------------------------------------------------
// K4: attention.  xg2[bt,n,:] = softmax_m(E_n . E_m) @ X[bt,m,:]
//     One thread per query row; Eq + acc in registers; 64-row K/V smem tiles.
//     Row max == diagonal (all E rows have equal norm after LN) -> single pass.
// ---------------------------------------------------------------------------
__global__ __launch_bounds__(64) void k_attn(const float* __restrict__ x)
{
    __shared__ float4 Em[64 * 16];   // 16 KB
    __shared__ float4 Xm[64 * 16];   // 16 KB
    int bt  = blockIdx.y;
    int row = blockIdx.x * 64 + threadIdx.x;
    const float* Ebt = g_E + (size_t)bt * NN * DD;
    const float* Xbt = x   + (size_t)bt * NN * DD;

    float4 eq[16];
    const float4* eqg = (const float4*)(Ebt + (size_t)row * DD);
    #pragma unroll
    for (int i = 0; i < 16; i++) eq[i] = eqg[i];

    float mii = 0.f;
    #pragma unroll
    for (int i = 0; i < 16; i++)
        mii += eq[i].x * eq[i].x + eq[i].y * eq[i].y + eq[i].z * eq[i].z + eq[i].w * eq[i].w;

    float4 acc[16];
    #pragma unroll
    for (int i = 0; i < 16; i++) acc[i] = make_float4(0.f, 0.f, 0.f, 0.f);
    float denom = 0.f;

    for (int m0 = 0; m0 < NN; m0 += 64) {
        __syncthreads();
        const float4* Eg = (const float4*)(Ebt + (size_t)m0 * DD);
        const float4* Xg = (const float4*)(Xbt + (size_t)m0 * DD);
        for (int i = threadIdx.x; i < 1024; i += 64) {
            Em[i] = Eg[i];
            Xm[i] = Xg[i];
        }
        __syncthreads();

        #pragma unroll 2
        for (int j = 0; j < 64; j++) {
            const float4* ej = &Em[j * 16];
            float s = 0.f;
            #pragma unroll
            for (int i = 0; i < 16; i++) {
                float4 e = ej[i];
                s += eq[i].x * e.x + eq[i].y * e.y + eq[i].z * e.z + eq[i].w * e.w;
            }
            float p = __expf(s - mii);
            denom += p;
            const float4* xj = &Xm[j * 16];
            #pragma unroll
            for (int i = 0; i < 16; i++) {
                float4 v = xj[i];
                acc[i].x += p * v.x;
                acc[i].y += p * v.y;
                acc[i].z += p * v.z;
                acc[i].w += p * v.w;
            }
        }
    }

    float inv = 1.0f / denom;
    float4* outp = (float4*)(g_xg2 + ((size_t)bt * NN + row) * DD);
    #pragma unroll
    for (int i = 0; i < 16; i++) {
        float4 v = acc[i];
        outp[i] = make_float4(v.x * inv, v.y * inv, v.z * inv, v.w * inv);
    }
}

// ---------------------------------------------------------------------------
// K5: out[bt,n,o] = x[bt,n,:].W1[n,:,o] + xg2[bt,n,:].W2[n,:,o] + bias[bt,o]
//     One block per node n; W[n] (32 KB) in smem, all 6 bt rows at once.
// ---------------------------------------------------------------------------
__global__ __launch_bounds__(384) void k_apply(const float* __restrict__ x,
                                               float* __restrict__ out)
{
    __shared__ float Ws[WC];            // 32 KB
    __shared__ float xs [BT * DD];
    __shared__ float x2s[BT * DD];
    int n = blockIdx.x;
    const float4* Wn = (const float4*)(g_W + (size_t)n * WC);
    for (int i = threadIdx.x; i < WC / 4; i += 384) ((float4*)Ws)[i] = Wn[i];
    for (int i = threadIdx.x; i < BT * 16; i += 384) {
        int bt = i >> 4, c4 = i & 15;
        ((float4*)xs )[i] = ((const float4*)(x     + ((size_t)bt * NN + n) * DD))[c4];
        ((float4*)x2s)[i] = ((const float4*)(g_xg2 + ((size_t)bt * NN + n) * DD))[c4];
    }
    __syncthreads();

    int bt = threadIdx.x / 64;
    int o  = threadIdx.x & 63;
    float s = g_bias[bt * DD + o];
    #pragma unroll
    for (int i = 0; i < DD; i++) s += xs [bt * DD + i] * Ws[i * DD + o];
    #pragma unroll
    for (int i = 0; i < DD; i++) s += x2s[bt * DD + i] * Ws[4096 + i * DD + o];
    out[((size_t)bt * NN + n) * DD + o] = s;
}

// ---------------------------------------------------------------------------
extern "C" void kernel_launch(void* const* d_in, const int* in_sizes, int n_in,
                              void* d_out, int out_size)
{
    const float* x        = (const float*)d_in[0];  // (2,3,4096,64)
    const float* node_emb = (const float*)d_in[1];  // (4096,64)
    const float* time_emb = (const float*)d_in[2];  // (2,3,64)
    const float* wpool    = (const float*)d_in[3];  // (64,2,64,64)
    const float* bpool    = (const float*)d_in[4];  // (64,64)
    const float* gamma    = (const float*)d_in[5];  // (64,)
    const float* beta     = (const float*)d_in[6];  // (64,)
    float* out = (float*)d_out;                     // (2,3,4096,64)

    k_ln   <<<(BT * NN) / 8, 256>>>(node_emb, time_emb, gamma, beta);
    k_bias <<<BT, DD>>>(time_emb, bpool);
    k_wgemm<<<dim3(WC / 64, NN / 128), 256>>>(node_emb, wpool);
    k_attn <<<dim3(NN / 64, BT), 64>>>(x);
    k_apply<<<NN, 384>>>(x, out);
}

// round 2
// speedup vs baseline: 1.0005x; 1.0005x over previous
#include <cuda_runtime.h>
#include <cstdint>

// Shapes (fixed by the problem)
#define BT   6          // b*t = 2*3
#define NN   4096       // nodes
#define DD   64         // di = do = de = 64
#define WC   8192       // 2*64*64 hypernet weight cols per node

// Scratch (device globals — no allocations allowed)
__device__ float g_E   [BT * NN * DD];   // layernormed embeddings, 6.3 MB
__device__ float g_W   [(size_t)NN * WC]; // per-node hypernet weights, 134 MB
__device__ float g_xg2 [BT * NN * DD];   // attention output, 6.3 MB
__device__ float g_bias[BT * DD];        // per-(b,t) bias

// ---------------------------------------------------------------------------
// K1: E[bt,n,:] = LayerNorm(node_emb[n,:] + time_emb[bt,:])  (warp per row)
// ---------------------------------------------------------------------------
__global__ __launch_bounds__(256) void k_ln(
    const float* __restrict__ node_emb, const float* __restrict__ time_emb,
    const float* __restrict__ gamma, const float* __restrict__ beta)
{
    int row  = blockIdx.x * 8 + (threadIdx.x >> 5);   // 0..BT*NN-1
    int lane = threadIdx.x & 31;
    if (row >= BT * NN) return;
    int bt = row >> 12;
    int n  = row & (NN - 1);

    float e0 = node_emb[n * DD + lane]       + time_emb[bt * DD + lane];
    float e1 = node_emb[n * DD + 32 + lane]  + time_emb[bt * DD + 32 + lane];
    float s  = e0 + e1;
    float s2 = e0 * e0 + e1 * e1;
    #pragma unroll
    for (int off = 16; off; off >>= 1) {
        s  += __shfl_xor_sync(0xffffffffu, s,  off);
        s2 += __shfl_xor_sync(0xffffffffu, s2, off);
    }
    float mu  = s * (1.0f / 64.0f);
    float var = s2 * (1.0f / 64.0f) - mu * mu;
    float rs  = rsqrtf(var + 1e-12f);
    float o0 = (e0 - mu) * rs * gamma[lane]      + beta[lane];
    float o1 = (e1 - mu) * rs * gamma[32 + lane] + beta[32 + lane];
    g_E[row * DD + lane]      = o0;
    g_E[row * DD + 32 + lane] = o1;
}

// ---------------------------------------------------------------------------
// K2: bias[bt,o] = time_emb[bt,:] . bias_pool[:,o]
// ---------------------------------------------------------------------------
__global__ void k_bias(const float* __restrict__ time_emb,
                       const float* __restrict__ bias_pool)
{
    int bt = blockIdx.x, o = threadIdx.x;
    float s = 0.f;
    #pragma unroll
    for (int d = 0; d < DD; d++) s += time_emb[bt * DD + d] * bias_pool[d * DD + o];
    g_bias[bt * DD + o] = s;
}

// ---------------------------------------------------------------------------
// K3: W[n, c] = node_emb[n,:] @ weights_pool[:, c]   (4096x64)@(64x8192)
//     Tile 128(n) x 64(c), 256 threads, 8x4 microtile, K=64 (single stage).
// ---------------------------------------------------------------------------
__global__ __launch_bounds__(256) void k_wgemm(
    const float* __restrict__ A,    // node_emb 4096x64
    const float* __restrict__ Bm)   // weights_pool as 64x8192
{
    __shared__ float As[64][128];   // [k][n]  32 KB
    __shared__ float Bs[64][64];    // [k][c]  16 KB
    int n0 = blockIdx.y * 128;
    int c0 = blockIdx.x * 64;
    int tid = threadIdx.x;

    // Load+transpose A tile: 128 rows x 16 float4
    #pragma unroll
    for (int p = 0; p < 8; p++) {
        int idx = p * 256 + tid;       // 0..2047
        int r   = idx >> 4;            // 0..127
        int c4  = idx & 15;            // 0..15
        float4 v = ((const float4*)A)[(size_t)(n0 + r) * 16 + c4];
        As[c4 * 4 + 0][r] = v.x;
        As[c4 * 4 + 1][r] = v.y;
        As[c4 * 4 + 2][r] = v.z;
        As[c4 * 4 + 3][r] = v.w;
    }
    // Load B tile: 64 rows x 16 float4
    #pragma unroll
    for (int p = 0; p < 4; p++) {
        int idx = p * 256 + tid;       // 0..1023
        int r   = idx >> 4;            // k
        int c4  = idx & 15;
        ((float4*)&Bs[r][0])[c4] = ((const float4*)(Bm + (size_t)r * WC + c0))[c4];
    }
    __syncthreads();

    int tx = tid & 15;   // col group (x4)
    int ty = tid >> 4;   // row group (x8)
    float acc[8][4];
    #pragma unroll
    for (int i = 0; i < 8; i++)
        #pragma unroll
        for (int j = 0; j < 4; j++) acc[i][j] = 0.f;

    #pragma unroll
    for (int k = 0; k < 64; k++) {
        float a[8], b[4];
        *(float4*)&a[0] = *(const float4*)&As[k][ty * 8 + 0];
        *(float4*)&a[4] = *(const float4*)&As[k][ty * 8 + 4];
        *(float4*)&b[0] = *(const float4*)&Bs[k][tx * 4];
        #pragma unroll
        for (int i = 0; i < 8; i++)
            #pragma unroll
            for (int j = 0; j < 4; j++) acc[i][j] += a[i] * b[j];
    }

    #pragma unroll
    for (int i = 0; i < 8; i++) {
        int n = n0 + ty * 8 + i;
        float4 v = make_float4(acc[i][0], acc[i][1], acc[i][2], acc[i][3]);
        *(float4*)(g_W + (size_t)n * WC + c0 + tx * 4) = v;
    }
}

// ---------------------------------------------------------------------------
// K4: attention.  xg2[bt,n,:] = softmax_m(E_n . E_m) @ X[bt,m,:]
//     One thread per query row; Eq + acc in registers; 64-row K/V smem tiles.
//     Row max == diagonal (all E rows have equal norm after LN) -> single pass.
// ---------------------------------------------------------------------------
__global__ __launch_bounds__(64) void k_attn(const float* __restrict__ x)
{
    __shared__ float4 Em[64 * 16];   // 16 KB
    __shared__ float4 Xm[64 * 16];   // 16 KB
    int bt  = blockIdx.y;
    int row = blockIdx.x * 64 + threadIdx.x;
    const float* Ebt = g_E + (size_t)bt * NN * DD;
    const float* Xbt = x   + (size_t)bt * NN * DD;

    float4 eq[16];
    const float4* eqg = (const float4*)(Ebt + (size_t)row * DD);
    #pragma unroll
    for (int i = 0; i < 16; i++) eq[i] = eqg[i];

    float mii = 0.f;
    #pragma unroll
    for (int i = 0; i < 16; i++)
        mii += eq[i].x * eq[i].x + eq[i].y * eq[i].y + eq[i].z * eq[i].z + eq[i].w * eq[i].w;

    float4 acc[16];
    #pragma unroll
    for (int i = 0; i < 16; i++) acc[i] = make_float4(0.f, 0.f, 0.f, 0.f);
    float denom = 0.f;

    for (int m0 = 0; m0 < NN; m0 += 64) {
        __syncthreads();
        const float4* Eg = (const float4*)(Ebt + (size_t)m0 * DD);
        const float4* Xg = (const float4*)(Xbt + (size_t)m0 * DD);
        for (int i = threadIdx.x; i < 1024; i += 64) {
            Em[i] = Eg[i];
            Xm[i] = Xg[i];
        }
        __syncthreads();

        #pragma unroll 2
        for (int j = 0; j < 64; j++) {
            const float4* ej = &Em[j * 16];
            float s = 0.f;
            #pragma unroll
            for (int i = 0; i < 16; i++) {
                float4 e = ej[i];
                s += eq[i].x * e.x + eq[i].y * e.y + eq[i].z * e.z + eq[i].w * e.w;
            }
            float p = __expf(s - mii);
            denom += p;
            const float4* xj = &Xm[j * 16];
            #pragma unroll
            for (int i = 0; i < 16; i++) {
                float4 v = xj[i];
                acc[i].x += p * v.x;
                acc[i].y += p * v.y;
                acc[i].z += p * v.z;
                acc[i].w += p * v.w;
            }
        }
    }

    float inv = 1.0f / denom;
    float4* outp = (float4*)(g_xg2 + ((size_t)bt * NN + row) * DD);
    #pragma unroll
    for (int i = 0; i < 16; i++) {
        float4 v = acc[i];
        outp[i] = make_float4(v.x * inv, v.y * inv, v.z * inv, v.w * inv);
    }
}

// ---------------------------------------------------------------------------
// K5: out[bt,n,o] = x[bt,n,:].W1[n,:,o] + xg2[bt,n,:].W2[n,:,o] + bias[bt,o]
//     One block per node n; W[n] (32 KB) in smem, all 6 bt rows at once.
// ---------------------------------------------------------------------------
__global__ __launch_bounds__(384) void k_apply(const float* __restrict__ x,
                                               float* __restrict__ out)
{
    __shared__ float Ws[WC];            // 32 KB
    __shared__ float xs [BT * DD];
    __shared__ float x2s[BT * DD];
    int n = blockIdx.x;
    const float4* Wn = (const float4*)(g_W + (size_t)n * WC);
    for (int i = threadIdx.x; i < WC / 4; i += 384) ((float4*)Ws)[i] = Wn[i];
    for (int i = threadIdx.x; i < BT * 16; i += 384) {
        int bt = i >> 4, c4 = i & 15;
        ((float4*)xs )[i] = ((const float4*)(x     + ((size_t)bt * NN + n) * DD))[c4];
        ((float4*)x2s)[i] = ((const float4*)(g_xg2 + ((size_t)bt * NN + n) * DD))[c4];
    }
    __syncthreads();

    int bt = threadIdx.x / 64;
    int o  = threadIdx.x & 63;
    float s = g_bias[bt * DD + o];
    #pragma unroll
    for (int i = 0; i < DD; i++) s += xs [bt * DD + i] * Ws[i * DD + o];
    #pragma unroll
    for (int i = 0; i < DD; i++) s += x2s[bt * DD + i] * Ws[4096 + i * DD + o];
    out[((size_t)bt * NN + n) * DD + o] = s;
}

// ---------------------------------------------------------------------------
extern "C" void kernel_launch(void* const* d_in, const int* in_sizes, int n_in,
                              void* d_out, int out_size)
{
    const float* x        = (const float*)d_in[0];  // (2,3,4096,64)
    const float* node_emb = (const float*)d_in[1];  // (4096,64)
    const float* time_emb = (const float*)d_in[2];  // (2,3,64)
    const float* wpool    = (const float*)d_in[3];  // (64,2,64,64)
    const float* bpool    = (const float*)d_in[4];  // (64,64)
    const float* gamma    = (const float*)d_in[5];  // (64,)
    const float* beta     = (const float*)d_in[6];  // (64,)
    float* out = (float*)d_out;                     // (2,3,4096,64)

    k_ln   <<<(BT * NN) / 8, 256>>>(node_emb, time_emb, gamma, beta);
    k_bias <<<BT, DD>>>(time_emb, bpool);
    k_wgemm<<<dim3(WC / 64, NN / 128), 256>>>(node_emb, wpool);
    k_attn <<<dim3(NN / 64, BT), 64>>>(x);
    k_apply<<<NN, 384>>>(x, out);
}

// round 3
// speedup vs baseline: 1.4655x; 1.4648x over previous
#include <cuda_runtime.h>
#include <cstdint>

// Shapes (fixed by the problem)
#define BT   6          // b*t = 2*3
#define NN   4096       // nodes
#define DD   64         // di = do = de = 64
#define WC   8192       // 2*64*64 hypernet weight cols per node

typedef unsigned long long u64;

// Scratch (device globals — no allocations allowed)
__device__ float g_E   [BT * NN * DD];    // layernormed embeddings
__device__ float g_mii [BT * NN];         // ||e_row||^2 (softmax shift)
__device__ float g_W   [(size_t)NN * WC]; // per-node hypernet weights, 134 MB
__device__ float g_xg2 [BT * NN * DD];    // attention output
__device__ float g_bias[BT * DD];         // per-(b,t) bias

#define FMA2(d, a, b, c) asm("fma.rn.f32x2 %0, %1, %2, %3;" : "=l"(d) : "l"(a), "l"(b), "l"(c))

__device__ __forceinline__ u64 dup2(float v) {
    u64 r;
    asm("mov.b64 %0, {%1, %1};" : "=l"(r) : "f"(v));
    return r;
}
__device__ __forceinline__ float2 unpack2(u64 v) {
    float lo, hi;
    asm("mov.b64 {%0, %1}, %2;" : "=f"(lo), "=f"(hi) : "l"(v));
    return make_float2(lo, hi);
}

// ---------------------------------------------------------------------------
// K1: E[bt,n,:] = LayerNorm(node_emb[n,:] + time_emb[bt,:]); also g_mii=||E||^2
// ---------------------------------------------------------------------------
__global__ __launch_bounds__(256) void k_ln(
    const float* __restrict__ node_emb, const float* __restrict__ time_emb,
    const float* __restrict__ gamma, const float* __restrict__ beta)
{
    int row  = blockIdx.x * 8 + (threadIdx.x >> 5);
    int lane = threadIdx.x & 31;
    if (row >= BT * NN) return;
    int bt = row >> 12;
    int n  = row & (NN - 1);

    float e0 = node_emb[n * DD + lane]      + time_emb[bt * DD + lane];
    float e1 = node_emb[n * DD + 32 + lane] + time_emb[bt * DD + 32 + lane];
    float s  = e0 + e1;
    float s2 = e0 * e0 + e1 * e1;
    #pragma unroll
    for (int off = 16; off; off >>= 1) {
        s  += __shfl_xor_sync(0xffffffffu, s,  off);
        s2 += __shfl_xor_sync(0xffffffffu, s2, off);
    }
    float mu  = s * (1.0f / 64.0f);
    float var = s2 * (1.0f / 64.0f) - mu * mu;
    float rs  = rsqrtf(var + 1e-12f);
    float o0 = (e0 - mu) * rs * gamma[lane]      + beta[lane];
    float o1 = (e1 - mu) * rs * gamma[32 + lane] + beta[32 + lane];
    g_E[row * DD + lane]      = o0;
    g_E[row * DD + 32 + lane] = o1;

    float q2 = o0 * o0 + o1 * o1;
    #pragma unroll
    for (int off = 16; off; off >>= 1)
        q2 += __shfl_xor_sync(0xffffffffu, q2, off);
    if (lane == 0) g_mii[row] = q2;
}

// ---------------------------------------------------------------------------
// K2: bias[bt,o] = time_emb[bt,:] . bias_pool[:,o]
// ---------------------------------------------------------------------------
__global__ void k_bias(const float* __restrict__ time_emb,
                       const float* __restrict__ bias_pool)
{
    int bt = blockIdx.x, o = threadIdx.x;
    float s = 0.f;
    #pragma unroll
    for (int d = 0; d < DD; d++) s += time_emb[bt * DD + d] * bias_pool[d * DD + o];
    g_bias[bt * DD + o] = s;
}

// ---------------------------------------------------------------------------
// K3: W[n, c] = node_emb[n,:] @ weights_pool[:, c]   (4096x64)@(64x8192)
// ---------------------------------------------------------------------------
__global__ __launch_bounds__(256) void k_wgemm(
    const float* __restrict__ A, const float* __restrict__ Bm)
{
    __shared__ float As[64][128];
    __shared__ float Bs[64][64];
    int n0 = blockIdx.y * 128;
    int c0 = blockIdx.x * 64;
    int tid = threadIdx.x;

    #pragma unroll
    for (int p = 0; p < 8; p++) {
        int idx = p * 256 + tid;
        int r   = idx >> 4;
        int c4  = idx & 15;
        float4 v = ((const float4*)A)[(size_t)(n0 + r) * 16 + c4];
        As[c4 * 4 + 0][r] = v.x;
        As[c4 * 4 + 1][r] = v.y;
        As[c4 * 4 + 2][r] = v.z;
        As[c4 * 4 + 3][r] = v.w;
    }
    #pragma unroll
    for (int p = 0; p < 4; p++) {
        int idx = p * 256 + tid;
        int r   = idx >> 4;
        int c4  = idx & 15;
        ((float4*)&Bs[r][0])[c4] = ((const float4*)(Bm + (size_t)r * WC + c0))[c4];
    }
    __syncthreads();

    int tx = tid & 15;
    int ty = tid >> 4;
    float acc[8][4];
    #pragma unroll
    for (int i = 0; i < 8; i++)
        #pragma unroll
        for (int j = 0; j < 4; j++) acc[i][j] = 0.f;

    #pragma unroll
    for (int k = 0; k < 64; k++) {
        float a[8], b[4];
        *(float4*)&a[0] = *(const float4*)&As[k][ty * 8 + 0];
        *(float4*)&a[4] = *(const float4*)&As[k][ty * 8 + 4];
        *(float4*)&b[0] = *(const float4*)&Bs[k][tx * 4];
        #pragma unroll
        for (int i = 0; i < 8; i++)
            #pragma unroll
            for (int j = 0; j < 4; j++) acc[i][j] += a[i] * b[j];
    }

    #pragma unroll
    for (int i = 0; i < 8; i++) {
        int n = n0 + ty * 8 + i;
        *(float4*)(g_W + (size_t)n * WC + c0 + tx * 4) =
            make_float4(acc[i][0], acc[i][1], acc[i][2], acc[i][3]);
    }
}

// ---------------------------------------------------------------------------
// K4: attention, register-tiled with fma.rn.f32x2.
//     Block: 64 queries, 128 threads (tq=tid&15 -> 4 queries, tk=tid>>4 -> 8 k / 8 d).
//     Stage A: S = Eq.Ek^T (Eq/Ek transposed [d][q|k] in smem), exp -> Ps.
//     Stage B: acc += P.X (X natural [k][d]).
// ---------------------------------------------------------------------------
struct AttnSmem {
    float Eqs[64][68];   // [d][q]
    float Eks[64][68];   // [d][k]
    float Xs [64][68];   // [k][d]
    float Ps [64][68];   // [k][q]
    float dsm[8][68];    // denominator partials [tk][q]
};
#define ATTN_SMEM_BYTES ((int)sizeof(AttnSmem))

__global__ __launch_bounds__(128) void k_attn(const float* __restrict__ x)
{
    extern __shared__ char smem_raw[];
    AttnSmem& sm = *(AttnSmem*)smem_raw;

    const int tid = threadIdx.x;
    const int tq  = tid & 15;     // owns queries q0 + tq*4 .. +3
    const int tk  = tid >> 4;     // owns k cols tk*8..+7 (A) / d cols tk*8..+7 (B)
    const int bt  = blockIdx.y;
    const int q0  = blockIdx.x * 64;

    const float* Ebt = g_E + (size_t)bt * NN * DD;
    const float* Xbt = x   + (size_t)bt * NN * DD;

    // Load Eq tile transposed: Eqs[d][q]
    #pragma unroll
    for (int it = 0; it < 8; it++) {
        int idx = it * 128 + tid;
        int q   = idx & 63;
        int c4  = idx >> 6;
        float4 v = *(const float4*)(Ebt + (size_t)(q0 + q) * DD + c4 * 4);
        sm.Eqs[c4 * 4 + 0][q] = v.x;
        sm.Eqs[c4 * 4 + 1][q] = v.y;
        sm.Eqs[c4 * 4 + 2][q] = v.z;
        sm.Eqs[c4 * 4 + 3][q] = v.w;
    }

    float mii[4];
    #pragma unroll
    for (int i = 0; i < 4; i++) mii[i] = g_mii[bt * NN + q0 + tq * 4 + i];

    u64 acc2[4][4];      // [q][d-pair]  (d = tk*8 + 2m, 2m+1)
    #pragma unroll
    for (int i = 0; i < 4; i++)
        #pragma unroll
        for (int m = 0; m < 4; m++) acc2[i][m] = 0ull;
    float dsum[4] = {0.f, 0.f, 0.f, 0.f};

    for (int m0 = 0; m0 < NN; m0 += 64) {
        __syncthreads();   // previous stage-B reads of Eks/Xs/Ps done

        // Load Ek tile transposed: Eks[d][k]
        #pragma unroll
        for (int it = 0; it < 8; it++) {
            int idx = it * 128 + tid;
            int k   = idx & 63;
            int c4  = idx >> 6;
            float4 v = *(const float4*)(Ebt + (size_t)(m0 + k) * DD + c4 * 4);
            sm.Eks[c4 * 4 + 0][k] = v.x;
            sm.Eks[c4 * 4 + 1][k] = v.y;
            sm.Eks[c4 * 4 + 2][k] = v.z;
            sm.Eks[c4 * 4 + 3][k] = v.w;
        }
        // Load X tile natural: Xs[k][d]
        #pragma unroll
        for (int it = 0; it < 8; it++) {
            int idx = it * 128 + tid;
            int k   = idx >> 4;
            int c4  = idx & 15;
            *(float4*)&sm.Xs[k][c4 * 4] =
                *(const float4*)(Xbt + (size_t)(m0 + k) * DD + c4 * 4);
        }
        __syncthreads();

        // Stage A: s[4q][8k] over 64 d
        u64 s2[4][4];
        #pragma unroll
        for (int i = 0; i < 4; i++)
            #pragma unroll
            for (int m = 0; m < 4; m++) s2[i][m] = 0ull;

        #pragma unroll 8
        for (int d = 0; d < 64; d++) {
            float4 av = *(const float4*)&sm.Eqs[d][tq * 4];
            ulonglong2 b01 = *(const ulonglong2*)&sm.Eks[d][tk * 8];
            ulonglong2 b23 = *(const ulonglong2*)&sm.Eks[d][tk * 8 + 4];
            u64 a[4];
            a[0] = dup2(av.x); a[1] = dup2(av.y); a[2] = dup2(av.z); a[3] = dup2(av.w);
            #pragma unroll
            for (int i = 0; i < 4; i++) {
                FMA2(s2[i][0], a[i], b01.x, s2[i][0]);
                FMA2(s2[i][1], a[i], b01.y, s2[i][1]);
                FMA2(s2[i][2], a[i], b23.x, s2[i][2]);
                FMA2(s2[i][3], a[i], b23.y, s2[i][3]);
            }
        }

        // exp + denominator partials
        float p[4][8];
        #pragma unroll
        for (int i = 0; i < 4; i++) {
            float dsi = 0.f;
            #pragma unroll
            for (int m = 0; m < 4; m++) {
                float2 sv = unpack2(s2[i][m]);
                float p0 = __expf(sv.x - mii[i]);
                float p1 = __expf(sv.y - mii[i]);
                p[i][2 * m]     = p0;
                p[i][2 * m + 1] = p1;
                dsi += p0 + p1;
            }
            dsum[i] += dsi;
        }
        // store P: Ps[k][q]
        #pragma unroll
        for (int j = 0; j < 8; j++) {
            *(float4*)&sm.Ps[tk * 8 + j][tq * 4] =
                make_float4(p[0][j], p[1][j], p[2][j], p[3][j]);
        }
        __syncthreads();

        // Stage B: acc[4q][8d] += P . X over 64 k
        #pragma unroll 8
        for (int k = 0; k < 64; k++) {
            float4 pv = *(const float4*)&sm.Ps[k][tq * 4];
            ulonglong2 x01 = *(const ulonglong2*)&sm.Xs[k][tk * 8];
            ulonglong2 x23 = *(const ulonglong2*)&sm.Xs[k][tk * 8 + 4];
            u64 a[4];
            a[0] = dup2(pv.x); a[1] = dup2(pv.y); a[2] = dup2(pv.z); a[3] = dup2(pv.w);
            #pragma unroll
            for (int i = 0; i < 4; i++) {
                FMA2(acc2[i][0], a[i], x01.x, acc2[i][0]);
                FMA2(acc2[i][1], a[i], x01.y, acc2[i][1]);
                FMA2(acc2[i][2], a[i], x23.x, acc2[i][2]);
                FMA2(acc2[i][3], a[i], x23.y, acc2[i][3]);
            }
        }
    }

    // denominator reduce across tk
    __syncthreads();
    #pragma unroll
    for (int i = 0; i < 4; i++) sm.dsm[tk][tq * 4 + i] = dsum[i];
    __syncthreads();
    float inv[4];
    #pragma unroll
    for (int i = 0; i < 4; i++) {
        float t = 0.f;
        #pragma unroll
        for (int t8 = 0; t8 < 8; t8++) t += sm.dsm[t8][tq * 4 + i];
        inv[i] = 1.0f / t;
    }

    // write xg2
    #pragma unroll
    for (int i = 0; i < 4; i++) {
        float2 a0 = unpack2(acc2[i][0]);
        float2 a1 = unpack2(acc2[i][1]);
        float2 a2 = unpack2(acc2[i][2]);
        float2 a3 = unpack2(acc2[i][3]);
        float* op = g_xg2 + ((size_t)bt * NN + q0 + tq * 4 + i) * DD + tk * 8;
        *(float4*)op       = make_float4(a0.x * inv[i], a0.y * inv[i],
                                         a1.x * inv[i], a1.y * inv[i]);
        *(float4*)(op + 4) = make_float4(a2.x * inv[i], a2.y * inv[i],
                                         a3.x * inv[i], a3.y * inv[i]);
    }
}

// ---------------------------------------------------------------------------
// K5: out[bt,n,o] = x[bt,n,:].W1[n,:,o] + xg2[bt,n,:].W2[n,:,o] + bias[bt,o]
// ---------------------------------------------------------------------------
__global__ __launch_bounds__(384) void k_apply(const float* __restrict__ x,
                                               float* __restrict__ out)
{
    __shared__ float Ws[WC];
    __shared__ float xs [BT * DD];
    __shared__ float x2s[BT * DD];
    int n = blockIdx.x;
    const float4* Wn = (const float4*)(g_W + (size_t)n * WC);
    for (int i = threadIdx.x; i < WC / 4; i += 384) ((float4*)Ws)[i] = Wn[i];
    for (int i = threadIdx.x; i < BT * 16; i += 384) {
        int bt = i >> 4, c4 = i & 15;
        ((float4*)xs )[i] = ((const float4*)(x     + ((size_t)bt * NN + n) * DD))[c4];
        ((float4*)x2s)[i] = ((const float4*)(g_xg2 + ((size_t)bt * NN + n) * DD))[c4];
    }
    __syncthreads();

    int bt = threadIdx.x / 64;
    int o  = threadIdx.x & 63;
    float s = g_bias[bt * DD + o];
    #pragma unroll
    for (int i = 0; i < DD; i++) s += xs [bt * DD + i] * Ws[i * DD + o];
    #pragma unroll
    for (int i = 0; i < DD; i++) s += x2s[bt * DD + i] * Ws[4096 + i * DD + o];
    out[((size_t)bt * NN + n) * DD + o] = s;
}

// ---------------------------------------------------------------------------
extern "C" void kernel_launch(void* const* d_in, const int* in_sizes, int n_in,
                              void* d_out, int out_size)
{
    const float* x        = (const float*)d_in[0];  // (2,3,4096,64)
    const float* node_emb = (const float*)d_in[1];  // (4096,64)
    const float* time_emb = (const float*)d_in[2];  // (2,3,64)
    const float* wpool    = (const float*)d_in[3];  // (64,2,64,64)
    const float* bpool    = (const float*)d_in[4];  // (64,64)
    const float* gamma    = (const float*)d_in[5];  // (64,)
    const float* beta     = (const float*)d_in[6];  // (64,)
    float* out = (float*)d_out;                     // (2,3,4096,64)

    cudaFuncSetAttribute(k_attn, cudaFuncAttributeMaxDynamicSharedMemorySize,
                         ATTN_SMEM_BYTES);

    k_ln   <<<(BT * NN) / 8, 256>>>(node_emb, time_emb, gamma, beta);
    k_bias <<<BT, DD>>>(time_emb, bpool);
    k_wgemm<<<dim3(WC / 64, NN / 128), 256>>>(node_emb, wpool);
    k_attn <<<dim3(NN / 64, BT), 128, ATTN_SMEM_BYTES>>>(x);
    k_apply<<<NN, 384>>>(x, out);
}